// round 1
// baseline (speedup 1.0000x reference)
#include <cuda_runtime.h>
#include <math.h>

#define SEQ   4096
#define LUTN  4096
#define PF    8

// Shared memory layout (dynamic, 64 KB):
//   float2 lut[4096]   : (sin, cos) table            32 KB
//   float  tphi[4096]  : mod(t*PHI, 2pi)             16 KB
//   int    toks[4096]  : this batch's token ids      16 KB
// After the scan, the base is reused for h staging for the projection.

__global__ void __launch_bounds__(64)
rin_scan_kernel(const int*  __restrict__ input_ids,
                const float* __restrict__ emb_table,
                const float* __restrict__ proj_w,
                const float* __restrict__ proj_b,
                float* __restrict__ out)
{
    extern __shared__ float sm[];
    float2* lut  = reinterpret_cast<float2*>(sm);        // [LUTN]
    float*  tphi = sm + 2 * LUTN;                        // [LUTN]
    int*    toks = reinterpret_cast<int*>(sm + 3 * LUTN);// [LUTN]

    const int d = threadIdx.x;   // channel 0..63
    const int b = blockIdx.x;    // batch

    // Constants, matching the reference's f32 values exactly.
    const float ANG_STEP = 0.0015339807878856412f;  // RN_f32(2*pi/4096)
    const float PHI_F    = 1.618033988749895f;      // RN_f32(phi)
    const float TWO_PI_F = 6.283185307179586f;      // RN_f32(2*pi)

    // ---- Stage tables + tokens into shared memory ----
    for (int i = d; i < LUTN; i += 64) {
        float ang = __fmul_rn(ANG_STEP, (float)i);
        lut[i] = make_float2(sinf(ang), cosf(ang));
        // t_phi[t] = fmod(RN(t*phi), 2pi)  (fmod is exact, matches XLA rem)
        float x = __fmul_rn((float)i, PHI_F);
        tphi[i] = fmodf(x, TWO_PI_F);
        toks[i] = input_ids[b * SEQ + i];
    }
    __syncthreads();

    // Constants for scaled Markstein division by 2*pi:
    //   fr = 4096 * RN(theta / 2pi)   (power-of-2 scaling is exact)
    const float R1 = __frcp_rn(TWO_PI_F);            // RN(1/2pi)
    const float R2 = __fmul_rn(R1, 4096.0f);         // exact scale
    const float C2 = __fmul_rn(TWO_PI_F, 2.44140625e-4f); // 2pi/4096, exact

    // ---- Prefetch pipeline (depth PF) ----
    float wv[PF], bv[PF], tv[PF];
#pragma unroll
    for (int j = 0; j < PF; ++j) {
        const float* row = emb_table + (size_t)toks[j] * 128;
        wv[j] = __ldg(row + d);
        bv[j] = __ldg(row + 64 + d);
        tv[j] = tphi[j];
    }

    float hr = 0.0f, hi = 0.0f;

#pragma unroll 8
    for (int t = 0; t < SEQ; ++t) {
        const int slot = t & (PF - 1);
        const float w  = wv[slot];
        const float bb = bv[slot];
        const float tp = tv[slot];

        const int tn = t + PF;
        if (tn < SEQ) {
            const float* row = emb_table + (size_t)toks[tn] * 128;
            wv[slot] = __ldg(row + d);
            bv[slot] = __ldg(row + 64 + d);
            tv[slot] = tphi[tn];
        }

        // Off-critical-path: depends only on prefetched w.
        const float lam = __fadd_rn(1.0f, fabsf(w));
        const float rc  = __frcp_rn(lam);            // correctly rounded 1/lam

        // q = RN(h / lam) via Markstein 3-op (12 cy on-chain instead of ~36)
        float q0r = __fmul_rn(hr, rc);
        float er  = __fmaf_rn(-lam, q0r, hr);
        float qr  = __fmaf_rn(er, rc, q0r);
        float q0i = __fmul_rn(hi, rc);
        float ei  = __fmaf_rn(-lam, q0i, hi);
        float qi  = __fmaf_rn(ei, rc, q0i);

        // theta = (h/lam + b) + tphi   (reference association order)
        float thr = __fadd_rn(__fadd_rn(qr, bb), tp);
        float thi = __fadd_rn(__fadd_rn(qi, bb), tp);

        // fr = 4096 * RN(theta/2pi); fi likewise
        float p0r = __fmul_rn(thr, R2);
        float e2r = __fmaf_rn(-C2, p0r, thr);
        float fr  = __fmaf_rn(e2r, R2, p0r);
        float p0i = __fmul_rn(thi, R2);
        float e2i = __fmaf_rn(-C2, p0i, thi);
        float fi  = __fmaf_rn(e2i, R2, p0i);

        // idx = floor(4096*f) mod 4096  ==  floor(frac*4096) mod 4096
        int ir = __float2int_rd(fr) & (LUTN - 1);
        int ii = __float2int_rd(fi) & (LUTN - 1);

        float2 tr = lut[ir];   // (sin, cos)
        float2 ti = lut[ii];

        const float sr = tr.x, cr = tr.y;
        const float si = ti.x, ci = ti.y;
        // Match reference: separate muls, then sub/add (no contraction)
        hr = __fsub_rn(__fmul_rn(cr, ci), __fmul_rn(sr, si));
        hi = __fadd_rn(__fmul_rn(cr, si), __fmul_rn(sr, ci));
    }

    // ---- Projection: out[b, j] = sum_k hc[k]*W[j,k] + bias[j] ----
    __syncthreads();              // everyone done reading lut
    sm[d]      = hr;              // hc[0:64]   = h_real
    sm[64 + d] = hi;              // hc[64:128] = h_imag
    __syncthreads();

#pragma unroll
    for (int rep = 0; rep < 2; ++rep) {
        const int j = d + rep * 64;
        const float* wrow = proj_w + j * 128;
        float acc = 0.0f;
#pragma unroll 16
        for (int k = 0; k < 128; ++k)
            acc = __fmaf_rn(sm[k], __ldg(wrow + k), acc);
        out[b * 128 + j] = __fadd_rn(acc, __ldg(proj_b + j));
    }
}

extern "C" void kernel_launch(void* const* d_in, const int* in_sizes, int n_in,
                              void* d_out, int out_size)
{
    const int*   ids = (const int*)d_in[0];
    const float* emb = (const float*)d_in[1];
    const float* W   = (const float*)d_in[2];
    const float* pb  = (const float*)d_in[3];
    float* out = (float*)d_out;

    const int B = in_sizes[0] / SEQ;   // 256
    const int smem_bytes = 4 * LUTN * 4;  // 64 KB

    cudaFuncSetAttribute(rin_scan_kernel,
                         cudaFuncAttributeMaxDynamicSharedMemorySize,
                         smem_bytes);

    rin_scan_kernel<<<B, 64, smem_bytes>>>(ids, emb, W, pb, out);
}

// round 3
// speedup vs baseline: 1.2322x; 1.2322x over previous
#include <cuda_runtime.h>
#include <math.h>

#define SEQ  4096
#define LUTN 4096
#define PF   16

// Shared memory (64 KB dynamic):
//   float2 lut[4096]  (sin, cos)        32 KB
//   float  tphi[4096] mod(t*phi,2pi)-hb 16 KB
//   int    toks[4096] batch tokens      16 KB
// State per thread: two integer LUT indices carried as low-12-bits of
// magic-biased floats. h = (cos, sin) of the SUMMED index -> one LDS/step.

__global__ void __launch_bounds__(64)
rin_kernel(const int*  __restrict__ ids,  const float* __restrict__ emb,
           const float* __restrict__ W,   const float* __restrict__ pb,
           float* __restrict__ out)
{
    extern __shared__ float sm[];
    float2* lut  = reinterpret_cast<float2*>(sm);
    float*  tphi = sm + 2 * LUTN;
    int*    toks = reinterpret_cast<int*>(sm + 3 * LUTN);

    const int d = threadIdx.x;   // channel 0..63
    const int b = blockIdx.x;    // batch

    const float ANG      = 0.0015339807878856412f;  // RN(2*pi/4096)
    const float PHI_F    = 1.618033988749895f;
    const float TWO_PI_F = 6.283185307179586f;
    const float MAGIC    = 12582912.0f;             // 1.5 * 2^23
    const float R2 = __fmul_rn(__frcp_rn(TWO_PI_F), 4096.0f);  // 4096/(2pi)
    const float HB = 0.5f * ANG;                    // half-bin (exact scale)

    // ---- Stage LUT + tphi (with -half-bin folded for the floor trick) + tokens ----
    for (int i = d; i < LUTN; i += 64) {
        float ang = __fmul_rn(ANG, (float)i);
        lut[i] = make_float2(sinf(ang), cosf(ang));
        tphi[i] = __fsub_rn(fmodf(__fmul_rn((float)i, PHI_F), TWO_PI_F), HB);
        toks[i] = ids[b * SEQ + i];
    }
    __syncthreads();

    // ---- Prefetch pipeline: raw w, b, tphi + double-prefetched tokens ----
    float wv[PF], bv[PF], tv[PF];
    int   tokv[PF];

#pragma unroll
    for (int s = 0; s < PF; ++s) tokv[s] = toks[s];

#define REFILL(slot_, tn_) do {                                           \
        const float* row_ = emb + (size_t)(unsigned)tokv[slot_] * 128;    \
        wv[slot_] = __ldg(row_ + d);                                      \
        bv[slot_] = __ldg(row_ + 64 + d);                                 \
        tv[slot_] = tphi[(tn_) & (SEQ - 1)];                              \
        tokv[slot_] = toks[((tn_) + PF) & (SEQ - 1)];                     \
    } while (0)

#pragma unroll
    for (int s = 0; s < PF; ++s) REFILL(s, s);
    // now wv/bv/tv[s] hold params for t=s; tokv[s] = toks[s+16]

    unsigned grb, gib;
    {   // t = 0: h == 0  ->  f = cb
        float cb0 = __fmul_rn(__fadd_rn(bv[0], tv[0]), R2);
        grb = __float_as_uint(__fadd_rn(cb0, MAGIC));
        gib = grb;
        REFILL(0, PF);   // params for t=16 into slot 0
    }

    // One step: param math is off-chain (inputs prefetched 16 steps ago);
    // the chain is fma -> fadd(magic) -> int add/mask -> LDS.64.
#define STEP(slot_, tn_) do {                                             \
        const float lam_ = __fadd_rn(1.0f, fabsf(wv[slot_]));             \
        const float rc2_ = __fmul_rn(__frcp_rn(lam_), R2);                \
        const float cb_  = __fmul_rn(__fadd_rn(bv[slot_], tv[slot_]), R2);\
        REFILL(slot_, tn_);                                               \
        unsigned j_ = (grb + gib) & (LUTN - 1);                           \
        float2 L_ = lut[j_];            /* (sin, cos) of summed angle */  \
        grb = __float_as_uint(__fadd_rn(__fmaf_rn(L_.y, rc2_, cb_), MAGIC)); \
        gib = __float_as_uint(__fadd_rn(__fmaf_rn(L_.x, rc2_, cb_), MAGIC)); \
    } while (0)

#pragma unroll
    for (int s = 1; s < PF; ++s) STEP(s, s + PF);

    for (int tb = 1; tb < SEQ / PF; ++tb) {
#pragma unroll
        for (int s = 0; s < PF; ++s) STEP(s, tb * PF + s + PF);
    }

    // Final h = lut[(ir+ii) & 4095]
    unsigned jf = (grb + gib) & (LUTN - 1);
    float2 Lf = lut[jf];
    float hr = Lf.y, hi = Lf.x;

    // ---- Projection: out[b, j] = sum_k hc[k] * W[j,k] + pb[j] ----
    __syncthreads();
    sm[d]      = hr;
    sm[64 + d] = hi;
    __syncthreads();

#pragma unroll
    for (int rep = 0; rep < 2; ++rep) {
        const int jo = d + rep * 64;
        const float* wrow = W + jo * 128;
        float acc = 0.0f;
#pragma unroll 16
        for (int k = 0; k < 128; ++k)
            acc = __fmaf_rn(sm[k], __ldg(wrow + k), acc);
        out[b * 128 + jo] = __fadd_rn(acc, __ldg(pb + jo));
    }
#undef STEP
#undef REFILL
}

extern "C" void kernel_launch(void* const* d_in, const int* in_sizes, int n_in,
                              void* d_out, int out_size)
{
    const int*   ids = (const int*)d_in[0];
    const float* emb = (const float*)d_in[1];
    const float* W   = (const float*)d_in[2];
    const float* pb  = (const float*)d_in[3];
    float* out = (float*)d_out;

    const int B = in_sizes[0] / SEQ;        // 256
    const int smem_bytes = 4 * LUTN * 4;    // 64 KB

    cudaFuncSetAttribute(rin_kernel,
                         cudaFuncAttributeMaxDynamicSharedMemorySize,
                         smem_bytes);

    rin_kernel<<<B, 64, smem_bytes>>>(ids, emb, W, pb, out);
}